// round 15
// baseline (speedup 1.0000x reference)
#include <cuda_runtime.h>

#define BATCH 4
#define DM 192
#define DI 192
#define LL 4096
#define KK 4
#define NS 16
#define RR 12
#define CPROJ 44
#define CT 32
#define NC 128

typedef unsigned long long u64;

__device__ __align__(16) float g_xin[BATCH*LL*DI];
__device__ __align__(16) float g_yin[BATCH*LL*DI];
__device__ __align__(16) float g_yinT[BATCH*LL*DI];
__device__ __align__(16) float g_pj[BATCH*KK*LL*RR];     // raw proj rows (chain order)
__device__ __align__(16) float g_Bs[BATCH*KK*LL*NS];
__device__ __align__(16) float g_Cs[BATCH*KK*LL*NS];
__device__ __align__(16) float g_sy[(size_t)BATCH*KK*LL*DI];  // PIXEL order [bk][p][d]
__device__ __align__(16) float g_anl2[KK*DI*NS];
__device__ __align__(16) float g_dsum[DI];
__device__ __align__(16) float g_H  [(size_t)BATCH*KK*DI*NC*NS];
__device__ __align__(16) float g_P  [(size_t)BATCH*KK*DI*NC*NS];
__device__ __align__(16) float g_Hin[(size_t)BATCH*KK*DI*NC*NS];
__device__ __align__(16) float g_dtw[KK*DI*RR];
__device__ __align__(16) float g_dtb[KK*DI];
__device__ int g_fast;

__device__ __forceinline__ float ex2f(float x){
    float r; asm("ex2.approx.ftz.f32 %0, %1;" : "=f"(r) : "f"(x)); return r;
}
__device__ __forceinline__ float lg2f(float x){
    float r; asm("lg2.approx.f32 %0, %1;" : "=f"(r) : "f"(x)); return r;
}
__device__ __forceinline__ u64 pk(float lo, float hi){
    u64 r; asm("mov.b64 %0, {%1,%2};" : "=l"(r) : "f"(lo), "f"(hi)); return r;
}
__device__ __forceinline__ void upk(u64 v, float& lo, float& hi){
    asm("mov.b64 {%0,%1}, %2;" : "=f"(lo), "=f"(hi) : "l"(v));
}
__device__ __forceinline__ u64 mul2(u64 a, u64 b){
    u64 r; asm("mul.rn.f32x2 %0, %1, %2;" : "=l"(r) : "l"(a), "l"(b)); return r;
}
__device__ __forceinline__ u64 fma2(u64 a, u64 b, u64 c){
    u64 r; asm("fma.rn.f32x2 %0, %1, %2, %3;" : "=l"(r) : "l"(a), "l"(b), "l"(c)); return r;
}
__device__ __forceinline__ float softplusf(float x){
    float t = ex2f(-fabsf(x) * 1.4426950408889634f);
    return fmaxf(x, 0.f) + 0.6931471805599453f * lg2f(1.0f + t);
}
__device__ __forceinline__ int inv_perm(int k, int p) {
    if (k == 0) return p;
    if (k == 1) return ((p & 63) << 6) | (p >> 6);
    if (k == 2) return LL - 1 - p;
    return LL - 1 - (((p & 63) << 6) | (p >> 6));
}
__device__ __forceinline__ void pows16p(float w, u64* P){
    float w2 = w*w, w4 = w2*w2;
    u64 W2 = pk(w2,w2), W4 = pk(w4,w4);
    P[0] = pk(w, w2);
    P[1] = mul2(P[0], W2);
    P[2] = mul2(P[0], W4);
    P[3] = mul2(P[1], W4);
    P[4] = mul2(P[2], W4);
    P[5] = mul2(P[3], W4);
    P[6] = mul2(P[4], W4);
    P[7] = mul2(P[5], W4);
}

__global__ void k0_init(const float* __restrict__ A_logs, const float* __restrict__ Ds,
                        const float* __restrict__ dtw, const float* __restrict__ dtb) {
    int t = threadIdx.x;
    if (t == 0) g_fast = 1;
    for (int i = t; i < KK*DI*NS; i += blockDim.x)
        g_anl2[i] = -expf(A_logs[i]) * 1.4426950408889634f;
    for (int i = t; i < KK*DI*RR; i += blockDim.x) g_dtw[i] = dtw[i];
    for (int i = t; i < KK*DI; i += blockDim.x)    g_dtb[i] = dtb[i];
    if (t < DI) g_dsum[t] = Ds[t] + Ds[DI + t] + Ds[2*DI + t] + Ds[3*DI + t];
    __syncthreads();
    int ok = 1;
    for (int i = t; i < KK*DI*NS; i += blockDim.x) {
        int n = i % NS;
        float base = g_anl2[i - n];
        float want = (float)(n + 1) * base;
        if (fabsf(g_anl2[i] - want) > 1e-3f * fabsf(want) + 1e-12f) ok = 0;
    }
    if (!ok) atomicExch(&g_fast, 0);
}

// ---------------- kernel 1: in_proj (f32x2) + yinT scatter -------------------
__global__ void k1_inproj(const float* __restrict__ x, const float* __restrict__ y,
                          const float* __restrict__ wx, const float* __restrict__ wy) {
    __shared__ __align__(16) float xs_s[16][64];
    __shared__ __align__(16) float ws_s[16][192];
    const float* src = blockIdx.y ? y : x;
    const float* w   = blockIdx.y ? wy : wx;
    float* dst       = blockIdx.y ? g_yin : g_xin;
    int tile = blockIdx.x;
    int b  = tile >> 6;
    int p0 = (tile & 63) * 64;
    int t  = threadIdx.x;
    int dg = t & 15;
    int pg = t >> 4;
    int d0 = dg * 12;
    int px = pg * 4;
    u64 acc2[4][6];
#pragma unroll
    for (int i = 0; i < 4; i++)
#pragma unroll
        for (int j = 0; j < 6; j++) acc2[i][j] = 0ull;

    for (int c0 = 0; c0 < DM; c0 += 16) {
        __syncthreads();
        for (int idx = t; idx < 16*64; idx += 256) {
            int cc = idx >> 6, j = idx & 63;
            xs_s[cc][j] = src[((size_t)(b*DM + c0 + cc))*LL + p0 + j];
        }
        for (int idx = t; idx < 16*192; idx += 256) {
            int cc = idx / 192, d = idx % 192;
            ws_s[cc][d] = w[(c0 + cc)*DI + d];
        }
        __syncthreads();
#pragma unroll
        for (int cc = 0; cc < 16; cc++) {
            float4 xv = *(const float4*)&xs_s[cc][px];
            ulonglong2 wq0 = *(const ulonglong2*)&ws_s[cc][d0];
            ulonglong2 wq1 = *(const ulonglong2*)&ws_s[cc][d0+4];
            ulonglong2 wq2 = *(const ulonglong2*)&ws_s[cc][d0+8];
            u64 wp[6] = {wq0.x, wq0.y, wq1.x, wq1.y, wq2.x, wq2.y};
            u64 xp[4] = {pk(xv.x,xv.x), pk(xv.y,xv.y), pk(xv.z,xv.z), pk(xv.w,xv.w)};
#pragma unroll
            for (int i = 0; i < 4; i++)
#pragma unroll
                for (int j = 0; j < 6; j++)
                    acc2[i][j] = fma2(xp[i], wp[j], acc2[i][j]);
        }
    }
#pragma unroll
    for (int i = 0; i < 4; i++) {
        float o[12];
#pragma unroll
        for (int j = 0; j < 6; j++) upk(acc2[i][j], o[2*j], o[2*j+1]);
        int p = p0 + px + i;
        float* op = dst + ((size_t)b*LL + p)*DI + d0;
        float4 q0 = make_float4(o[0], o[1], o[2], o[3]);
        float4 q1 = make_float4(o[4], o[5], o[6], o[7]);
        float4 q2 = make_float4(o[8], o[9], o[10], o[11]);
        *(float4*)(op + 0) = q0;
        *(float4*)(op + 4) = q1;
        *(float4*)(op + 8) = q2;
        if (blockIdx.y) {
            int tp = ((p & 63) << 6) | (p >> 6);
            float* ot = g_yinT + ((size_t)b*LL + tp)*DI + d0;
            *(float4*)(ot + 0) = q0;
            *(float4*)(ot + 4) = q1;
            *(float4*)(ot + 8) = q2;
        }
    }
}

// ---------------- kernel 2: x_proj as k1-style output-tile GEMM --------------
#define XS_PAD 68
#define WS_PAD 196
__global__ __launch_bounds__(256) void k2_xproj(const float* __restrict__ xpw) {
    __shared__ __align__(16) float xs_s[16][XS_PAD];
    __shared__ __align__(16) float ws_s[16][WS_PAD];
    int p0 = blockIdx.x * 64;
    int b  = blockIdx.y;
    int t  = threadIdx.x;
    int cg = t & 15;
    int pg = t >> 4;
    int c0 = cg * 12;
    int px = pg * 4;
    u64 acc2[4][6];
#pragma unroll
    for (int i = 0; i < 4; i++)
#pragma unroll
        for (int j = 0; j < 6; j++) acc2[i][j] = 0ull;

    for (int d0 = 0; d0 < DI; d0 += 16) {
        __syncthreads();
        for (int idx = t; idx < 16*64; idx += 256) {
            int dd = idx & 15, l = idx >> 4;
            xs_s[dd][l] = g_xin[((size_t)b*LL + p0 + l)*DI + d0 + dd];
        }
        for (int idx = t; idx < 16*192; idx += 256) {
            int dd = idx & 15, kcs = idx >> 4;
            int k = kcs / 48, cc = kcs % 48;
            ws_s[dd][kcs] = (cc < CPROJ) ? xpw[((size_t)(k*CPROJ + cc))*DI + d0 + dd] : 0.f;
        }
        __syncthreads();
#pragma unroll
        for (int dd = 0; dd < 16; dd++) {
            float4 xv = *(const float4*)&xs_s[dd][px];
            ulonglong2 wq0 = *(const ulonglong2*)&ws_s[dd][c0];
            ulonglong2 wq1 = *(const ulonglong2*)&ws_s[dd][c0+4];
            ulonglong2 wq2 = *(const ulonglong2*)&ws_s[dd][c0+8];
            u64 wp[6] = {wq0.x, wq0.y, wq1.x, wq1.y, wq2.x, wq2.y};
            u64 xp[4] = {pk(xv.x,xv.x), pk(xv.y,xv.y), pk(xv.z,xv.z), pk(xv.w,xv.w)};
#pragma unroll
            for (int i = 0; i < 4; i++)
#pragma unroll
                for (int j = 0; j < 6; j++)
                    acc2[i][j] = fma2(xp[i], wp[j], acc2[i][j]);
        }
    }

    int k  = cg >> 2;
    int cl = (cg & 3) * 12;
    size_t rowbase = (size_t)(b*KK + k)*LL;
#pragma unroll
    for (int i = 0; i < 4; i++) {
        int p = p0 + px + i;
        int l = inv_perm(k, p);
        float o[12];
#pragma unroll
        for (int j = 0; j < 6; j++) upk(acc2[i][j], o[2*j], o[2*j+1]);
        if (cl == 0) {
            float* dst = g_pj + (rowbase + l)*RR;
            *(float4*)(dst + 0) = make_float4(o[0], o[1], o[2], o[3]);
            *(float4*)(dst + 4) = make_float4(o[4], o[5], o[6], o[7]);
            *(float4*)(dst + 8) = make_float4(o[8], o[9], o[10], o[11]);
        } else if (cl == 12) {
            float* dst = g_Bs + (rowbase + l)*NS;
            *(float4*)(dst + 0) = make_float4(o[0], o[1], o[2], o[3]);
            *(float4*)(dst + 4) = make_float4(o[4], o[5], o[6], o[7]);
            *(float4*)(dst + 8) = make_float4(o[8], o[9], o[10], o[11]);
        } else if (cl == 24) {
            *(float4*)(g_Bs + (rowbase + l)*NS + 12) = make_float4(o[0], o[1], o[2], o[3]);
            *(float4*)(g_Cs + (rowbase + l)*NS + 0)  = make_float4(o[4], o[5], o[6], o[7]);
            *(float4*)(g_Cs + (rowbase + l)*NS + 4)  = make_float4(o[8], o[9], o[10], o[11]);
        } else {
            *(float4*)(g_Cs + (rowbase + l)*NS + 8)  = make_float4(o[0], o[1], o[2], o[3]);
            *(float4*)(g_Cs + (rowbase + l)*NS + 12) = make_float4(o[4], o[5], o[6], o[7]);
        }
    }
}

// u-stream: all 4 directions contiguous via yin / yinT
__device__ __forceinline__ const float* u_base(int k, int b, int l0, int d, int& ustep) {
    if (k == 0) { ustep =  DI; return g_yin  + ((size_t)b*LL + l0)*DI + d; }
    if (k == 1) { ustep =  DI; return g_yinT + ((size_t)b*LL + l0)*DI + d; }
    if (k == 2) { ustep = -DI; return g_yin  + ((size_t)b*LL + (LL-1-l0))*DI + d; }
    ustep = -DI; return g_yinT + ((size_t)b*LL + (LL-1-l0))*DI + d;
}

// y-output in PIXEL order: start pixel + uniform stride per direction
__device__ __forceinline__ float* y_base(int k, size_t bk, int l0, int d, int& ostep) {
    int pstart;
    if (k == 0)      { pstart = l0;                                  ostep =  DI;    }
    else if (k == 1) { pstart = ((l0 & 63) << 6) | (l0 >> 6);        ostep =  64*DI; }
    else if (k == 2) { pstart = LL - 1 - l0;                          ostep = -DI;    }
    else { int q = LL - 1 - l0; pstart = ((q & 63) << 6) | (q >> 6);  ostep = -64*DI; }
    return g_sy + (bk*LL + (size_t)pstart)*DI + d;
}

// delta recompute: 6 r-pair fma2 against smem proj row + softplus
__device__ __forceinline__ float delta_step(const u64* wp2, float bias, const float* pjrow){
    const u64* pj = (const u64*)pjrow;
    u64 a2 = fma2(wp2[0], pj[0], 0ull);
    a2 = fma2(wp2[1], pj[1], a2);
    a2 = fma2(wp2[2], pj[2], a2);
    a2 = fma2(wp2[3], pj[3], a2);
    a2 = fma2(wp2[4], pj[4], a2);
    a2 = fma2(wp2[5], pj[5], a2);
    float alo, ahi; upk(a2, alo, ahi);
    return softplusf(bias + alo + ahi);
}

// ---- pass1: recursion + C-dot + y_local (pixel order) + chunk summaries -----
__global__ __launch_bounds__(192, 6) void k3_pass1() {
    __shared__ __align__(16) float sB[CT*NS];
    __shared__ __align__(16) float sC[CT*NS];
    __shared__ __align__(16) float sPJ[CT*RR];
    int c = blockIdx.x, k = blockIdx.y, b = blockIdx.z;
    int d = threadIdx.x;
    size_t bk = (size_t)(b*KK + k);
    int l0 = c * CT;
    {
        const float4* Bg = (const float4*)(g_Bs + (bk*LL + (size_t)l0)*NS);
        const float4* Cg = (const float4*)(g_Cs + (bk*LL + (size_t)l0)*NS);
        const float4* Pg = (const float4*)(g_pj + (bk*LL + (size_t)l0)*RR);
        float4* sB4 = (float4*)sB;
        float4* sC4 = (float4*)sC;
        float4* sP4 = (float4*)sPJ;
        for (int i = d; i < CT*NS/4; i += 192) { sB4[i] = Bg[i]; sC4[i] = Cg[i]; }
        for (int i = d; i < CT*RR/4; i += 192) sP4[i] = Pg[i];
    }
    __syncthreads();

    float* op; int ostep;
    op = y_base(k, bk, l0, d, ostep);
    int ustep;
    const float* up = u_base(k, b, l0, d, ustep);
    size_t ch = bk*DI + d;

    const float4* wr4 = (const float4*)(g_dtw + ((size_t)k*DI + d)*RR);
    float4 w0 = wr4[0], w1 = wr4[1], w2 = wr4[2];
    u64 wp2[6] = { pk(w0.x,w0.y), pk(w0.z,w0.w), pk(w1.x,w1.y),
                   pk(w1.z,w1.w), pk(w2.x,w2.y), pk(w2.z,w2.w) };
    float bias = g_dtb[k*DI + d];

    if (g_fast) {
        float an0 = g_anl2[((size_t)k*DI + d)*NS];
        u64 h2[8];
#pragma unroll
        for (int i = 0; i < 8; i++) h2[i] = 0ull;
        float S = 0.f;
#pragma unroll 4
        for (int t = 0; t < CT; t++) {
            float dlt = delta_step(wp2, bias, &sPJ[t*RR]);
            float uv  = up[(size_t)t*ustep];
            const u64* Bw = (const u64*)&sB[t*NS];
            const u64* Cw = (const u64*)&sC[t*NS];
            u64 P[8]; pows16p(ex2f(dlt * an0), P);
            float du = dlt * uv;
            u64 DU = pk(du, du);
            u64 Y = 0ull;
#pragma unroll
            for (int i = 0; i < 8; i++) {
                h2[i] = fma2(P[i], h2[i], mul2(DU, Bw[i]));
                Y = fma2(h2[i], Cw[i], Y);
            }
            float ylo, yhi; upk(Y, ylo, yhi);
            op[(size_t)t*ostep] = ylo + yhi;
            S += dlt;
        }
        u64* Hp = (u64*)(g_H + (ch*NC + c)*NS);
        u64* Pp = (u64*)(g_P + (ch*NC + c)*NS);
        u64 Q[8]; pows16p(ex2f(an0 * S), Q);
#pragma unroll
        for (int i = 0; i < 8; i++) { Hp[i] = h2[i]; Pp[i] = Q[i]; }
    } else {
        float an[NS];
        const float* ap = g_anl2 + ((size_t)k*DI + d)*NS;
#pragma unroll
        for (int n = 0; n < NS; n++) an[n] = ap[n];
        float h[NS];
#pragma unroll
        for (int n = 0; n < NS; n++) h[n] = 0.f;
        float S = 0.f;
        for (int t = 0; t < CT; t++) {
            float dlt = delta_step(wp2, bias, &sPJ[t*RR]);
            float uv  = up[(size_t)t*ustep];
            float du = dlt * uv;
            const float* Bp = &sB[t*NS];
            const float* Cp = &sC[t*NS];
            float y = 0.f;
#pragma unroll
            for (int n = 0; n < NS; n++) {
                h[n] = fmaf(ex2f(dlt*an[n]), h[n], du * Bp[n]);
                y = fmaf(h[n], Cp[n], y);
            }
            op[(size_t)t*ostep] = y;
            S += dlt;
        }
        float* Hp = g_H + (ch*NC + c)*NS;
        float* Pp = g_P + (ch*NC + c)*NS;
#pragma unroll
        for (int n = 0; n < NS; n++) { Hp[n] = h[n]; Pp[n] = ex2f(an[n]*S); }
    }
}

__global__ void k3_comb() {
    int t = blockIdx.x * blockDim.x + threadIdx.x;
    int n = t & 15;
    size_t ch = (size_t)(t >> 4);
    const float* __restrict__ Hp = g_H   + ch*NC*NS + n;
    const float* __restrict__ Pp = g_P   + ch*NC*NS + n;
    float*       __restrict__ Ip = g_Hin + ch*NC*NS + n;
    float h = 0.f;
#pragma unroll 4
    for (int c = 0; c < NC; c++) {
        Ip[c*NS] = h;
        h = fmaf(Pp[c*NS], h, Hp[c*NS]);
    }
}

// ---- pass2: chain-free carry correction (recomputes delta prefix) -----------
__global__ __launch_bounds__(192, 6) void k3_pass2() {
    __shared__ __align__(16) float sC[CT*NS];
    __shared__ __align__(16) float sPJ[CT*RR];
    int c = blockIdx.x, k = blockIdx.y, b = blockIdx.z;
    int d = threadIdx.x;
    size_t bk = (size_t)(b*KK + k);
    int l0 = c * CT;
    {
        const float4* Cg = (const float4*)(g_Cs + (bk*LL + (size_t)l0)*NS);
        const float4* Pg = (const float4*)(g_pj + (bk*LL + (size_t)l0)*RR);
        float4* sC4 = (float4*)sC;
        float4* sP4 = (float4*)sPJ;
        for (int i = d; i < CT*NS/4; i += 192) sC4[i] = Cg[i];
        for (int i = d; i < CT*RR/4; i += 192) sP4[i] = Pg[i];
    }
    __syncthreads();

    const float4* wr4 = (const float4*)(g_dtw + ((size_t)k*DI + d)*RR);
    float4 w0 = wr4[0], w1 = wr4[1], w2 = wr4[2];
    u64 wp2[6] = { pk(w0.x,w0.y), pk(w0.z,w0.w), pk(w1.x,w1.y),
                   pk(w1.z,w1.w), pk(w2.x,w2.y), pk(w2.z,w2.w) };
    float bias = g_dtb[k*DI + d];

    float* yp; int ostep;
    yp = y_base(k, bk, l0, d, ostep);
    size_t ch = bk*DI + d;

    if (g_fast) {
        float an0 = g_anl2[((size_t)k*DI + d)*NS];
        const u64* Ip = (const u64*)(g_Hin + (ch*NC + c)*NS);
        u64 hin[8];
#pragma unroll
        for (int i = 0; i < 8; i++) hin[i] = Ip[i];
        float S = 0.f;
#pragma unroll 4
        for (int t = 0; t < CT; t++) {
            S += delta_step(wp2, bias, &sPJ[t*RR]);
            u64 P[8]; pows16p(ex2f(an0 * S), P);
            const u64* Cw = (const u64*)&sC[t*NS];
            u64 Y = 0ull;
#pragma unroll
            for (int i = 0; i < 8; i++)
                Y = fma2(mul2(P[i], hin[i]), Cw[i], Y);
            float ylo, yhi; upk(Y, ylo, yhi);
            yp[(size_t)t*ostep] += ylo + yhi;
        }
    } else {
        float an[NS];
        const float* ap = g_anl2 + ((size_t)k*DI + d)*NS;
#pragma unroll
        for (int n = 0; n < NS; n++) an[n] = ap[n];
        const float* Ip = g_Hin + (ch*NC + c)*NS;
        float hin[NS];
#pragma unroll
        for (int n = 0; n < NS; n++) hin[n] = Ip[n];
        float S = 0.f;
        for (int t = 0; t < CT; t++) {
            S += delta_step(wp2, bias, &sPJ[t*RR]);
            const float* Cp = &sC[t*NS];
            float y = 0.f;
#pragma unroll
            for (int n = 0; n < NS; n++)
                y = fmaf(ex2f(an[n]*S) * hin[n], Cp[n], y);
            yp[(size_t)t*ostep] += y;
        }
    }
}

// ---------------- kernel 5: merge + LN + out_proj (float4 output stores) -----
__global__ __launch_bounds__(256) void k5_merge(
        const float* __restrict__ gamma, const float* __restrict__ beta,
        const float* __restrict__ opw, float* __restrict__ out) {
    __shared__ __align__(16) float ym_s[64*DI];
    __shared__ __align__(16) float W_s[16*DI];
    __shared__ float mu_s[64], rs_s[64];
    int b = blockIdx.y;
    int p0 = blockIdx.x * 64;
    int t = threadIdx.x;
    size_t bb = (size_t)b * KK;

    for (int idx = t; idx < 64*DI/4; idx += 256) {
        size_t off = (size_t)p0*DI + idx*4;
        float4 v0 = *(const float4*)&g_sy[((bb + 0)*LL)*DI + off];
        float4 v1 = *(const float4*)&g_sy[((bb + 1)*LL)*DI + off];
        float4 v2 = *(const float4*)&g_sy[((bb + 2)*LL)*DI + off];
        float4 v3 = *(const float4*)&g_sy[((bb + 3)*LL)*DI + off];
        float4 u  = *(const float4*)&g_yin[((size_t)b*LL)*DI + off];
        int dd = (idx*4) % DI;
        float4 ds = *(const float4*)&g_dsum[dd];
        float4 r;
        r.x = v0.x + v1.x + v2.x + v3.x + ds.x * u.x;
        r.y = v0.y + v1.y + v2.y + v3.y + ds.y * u.y;
        r.z = v0.z + v1.z + v2.z + v3.z + ds.z * u.z;
        r.w = v0.w + v1.w + v2.w + v3.w + ds.w * u.w;
        *(float4*)&ym_s[idx*4] = r;
    }
    __syncthreads();

    {
        int warp = t >> 5, lane = t & 31;
        int pl  = warp*8 + (lane >> 2);
        int sub = lane & 3;
        float s = 0.f, s2 = 0.f;
        for (int j = sub; j < DI; j += 4) { float v = ym_s[pl*DI + j]; s += v; s2 += v*v; }
        s  += __shfl_xor_sync(0xffffffffu, s, 2);  s2 += __shfl_xor_sync(0xffffffffu, s2, 2);
        s  += __shfl_xor_sync(0xffffffffu, s, 1);  s2 += __shfl_xor_sync(0xffffffffu, s2, 1);
        if (sub == 0) {
            float mu  = s * (1.f/DI);
            float var = s2 * (1.f/DI) - mu*mu;
            mu_s[pl] = mu;
            rs_s[pl] = rsqrtf(var + 1e-5f);
        }
    }
    __syncthreads();

    for (int idx = t; idx < 64*DI; idx += 256) {
        int pl = idx / DI, d = idx % DI;
        ym_s[idx] = (ym_s[idx] - mu_s[pl]) * rs_s[pl] * gamma[d] + beta[d];
    }

    int c0 = (t & 15) * 12;
    int px = (t >> 4) * 4;
    u64 acc2[4][6];
#pragma unroll
    for (int i = 0; i < 4; i++)
#pragma unroll
        for (int j = 0; j < 6; j++) acc2[i][j] = 0ull;

    for (int dc = 0; dc < DI; dc += 16) {
        __syncthreads();
        for (int idx = t; idx < 16*DI; idx += 256)
            W_s[idx] = opw[(dc + idx/DI)*DM + (idx % DI)];
        __syncthreads();
#pragma unroll
        for (int dd = 0; dd < 16; dd++) {
            ulonglong2 wq0 = *(const ulonglong2*)&W_s[dd*DI + c0];
            ulonglong2 wq1 = *(const ulonglong2*)&W_s[dd*DI + c0 + 4];
            ulonglong2 wq2 = *(const ulonglong2*)&W_s[dd*DI + c0 + 8];
            u64 wp[6] = {wq0.x, wq0.y, wq1.x, wq1.y, wq2.x, wq2.y};
#pragma unroll
            for (int i = 0; i < 4; i++) {
                float yv = ym_s[(px + i)*DI + dc + dd];
                u64 yp2 = pk(yv, yv);
#pragma unroll
                for (int j = 0; j < 6; j++)
                    acc2[i][j] = fma2(yp2, wp[j], acc2[i][j]);
            }
        }
    }
    {
        float o[4][12];
#pragma unroll
        for (int i = 0; i < 4; i++)
#pragma unroll
            for (int j = 0; j < 6; j++) upk(acc2[i][j], o[i][2*j], o[i][2*j+1]);
#pragma unroll
        for (int j = 0; j < 12; j++) {
            float4 v = make_float4(o[0][j], o[1][j], o[2][j], o[3][j]);
            *(float4*)&out[((size_t)(b*DM + c0 + j))*LL + p0 + px] = v;
        }
    }
}

extern "C" void kernel_launch(void* const* d_in, const int* in_sizes, int n_in,
                              void* d_out, int out_size) {
    const float* x    = (const float*)d_in[0];
    const float* y    = (const float*)d_in[1];
    const float* wx   = (const float*)d_in[2];
    const float* wy   = (const float*)d_in[3];
    const float* xpw  = (const float*)d_in[4];
    const float* dtw  = (const float*)d_in[5];
    const float* dtb  = (const float*)d_in[6];
    const float* Alog = (const float*)d_in[7];
    const float* Ds   = (const float*)d_in[8];
    const float* gam  = (const float*)d_in[9];
    const float* bet  = (const float*)d_in[10];
    const float* opw  = (const float*)d_in[11];
    float* out = (float*)d_out;

    k0_init<<<1, 256>>>(Alog, Ds, dtw, dtb);
    k1_inproj<<<dim3(256, 2), 256>>>(x, y, wx, wy);
    k2_xproj<<<dim3(LL/64, BATCH), 256>>>(xpw);
    k3_pass1<<<dim3(NC, KK, BATCH), 192>>>();
    k3_comb<<<192, 256>>>();
    k3_pass2<<<dim3(NC, KK, BATCH), 192>>>();
    k5_merge<<<dim3(LL/64, BATCH), 256>>>(gam, bet, opw, out);
}

// round 17
// speedup vs baseline: 1.0166x; 1.0166x over previous
#include <cuda_runtime.h>

#define BATCH 4
#define DM 192
#define DI 192
#define LL 4096
#define KK 4
#define NS 16
#define RR 12
#define CPROJ 44
#define CT 32
#define NC 128

typedef unsigned long long u64;

__device__ __align__(16) float g_xin[BATCH*LL*DI];
__device__ __align__(16) float g_yin[BATCH*LL*DI];
__device__ __align__(16) float g_yinT[BATCH*LL*DI];
__device__ __align__(16) float g_pj[BATCH*KK*LL*RR];     // raw proj rows (chain order)
__device__ __align__(16) float g_Bs[BATCH*KK*LL*NS];
__device__ __align__(16) float g_Cs[BATCH*KK*LL*NS];
__device__ __align__(16) float g_sy[(size_t)BATCH*KK*LL*DI];  // PIXEL order [bk][p][d]
__device__ __align__(16) float g_anl2[KK*DI*NS];
__device__ __align__(16) float g_dsum[DI];
__device__ __align__(16) float g_H  [(size_t)BATCH*KK*DI*NC*NS];
__device__ __align__(16) float g_P  [(size_t)BATCH*KK*DI*NC*NS];
__device__ __align__(16) float g_Hin[(size_t)BATCH*KK*DI*NC*NS];
__device__ __align__(16) float g_dtw[KK*DI*RR];
__device__ __align__(16) float g_dtb[KK*DI];
__device__ int g_fast;

__device__ __forceinline__ float ex2f(float x){
    float r; asm("ex2.approx.ftz.f32 %0, %1;" : "=f"(r) : "f"(x)); return r;
}
__device__ __forceinline__ float lg2f(float x){
    float r; asm("lg2.approx.f32 %0, %1;" : "=f"(r) : "f"(x)); return r;
}
__device__ __forceinline__ u64 pk(float lo, float hi){
    u64 r; asm("mov.b64 %0, {%1,%2};" : "=l"(r) : "f"(lo), "f"(hi)); return r;
}
__device__ __forceinline__ void upk(u64 v, float& lo, float& hi){
    asm("mov.b64 {%0,%1}, %2;" : "=f"(lo), "=f"(hi) : "l"(v));
}
__device__ __forceinline__ u64 mul2(u64 a, u64 b){
    u64 r; asm("mul.rn.f32x2 %0, %1, %2;" : "=l"(r) : "l"(a), "l"(b)); return r;
}
__device__ __forceinline__ u64 fma2(u64 a, u64 b, u64 c){
    u64 r; asm("fma.rn.f32x2 %0, %1, %2, %3;" : "=l"(r) : "l"(a), "l"(b), "l"(c)); return r;
}
__device__ __forceinline__ float softplusf(float x){
    float t = ex2f(-fabsf(x) * 1.4426950408889634f);
    return fmaxf(x, 0.f) + 0.6931471805599453f * lg2f(1.0f + t);
}
__device__ __forceinline__ int inv_perm(int k, int p) {
    if (k == 0) return p;
    if (k == 1) return ((p & 63) << 6) | (p >> 6);
    if (k == 2) return LL - 1 - p;
    return LL - 1 - (((p & 63) << 6) | (p >> 6));
}
__device__ __forceinline__ void pows16p(float w, u64* P){
    float w2 = w*w, w4 = w2*w2;
    u64 W2 = pk(w2,w2), W4 = pk(w4,w4);
    P[0] = pk(w, w2);
    P[1] = mul2(P[0], W2);
    P[2] = mul2(P[0], W4);
    P[3] = mul2(P[1], W4);
    P[4] = mul2(P[2], W4);
    P[5] = mul2(P[3], W4);
    P[6] = mul2(P[4], W4);
    P[7] = mul2(P[5], W4);
}

__global__ void k0_init(const float* __restrict__ A_logs, const float* __restrict__ Ds,
                        const float* __restrict__ dtw, const float* __restrict__ dtb) {
    int t = threadIdx.x;
    if (t == 0) g_fast = 1;
    for (int i = t; i < KK*DI*NS; i += blockDim.x)
        g_anl2[i] = -expf(A_logs[i]) * 1.4426950408889634f;
    for (int i = t; i < KK*DI*RR; i += blockDim.x) g_dtw[i] = dtw[i];
    for (int i = t; i < KK*DI; i += blockDim.x)    g_dtb[i] = dtb[i];
    if (t < DI) g_dsum[t] = Ds[t] + Ds[DI + t] + Ds[2*DI + t] + Ds[3*DI + t];
    __syncthreads();
    int ok = 1;
    for (int i = t; i < KK*DI*NS; i += blockDim.x) {
        int n = i % NS;
        float base = g_anl2[i - n];
        float want = (float)(n + 1) * base;
        if (fabsf(g_anl2[i] - want) > 1e-3f * fabsf(want) + 1e-12f) ok = 0;
    }
    if (!ok) atomicExch(&g_fast, 0);
}

// ---------------- kernel 1: in_proj (f32x2) + yinT scatter -------------------
__global__ void k1_inproj(const float* __restrict__ x, const float* __restrict__ y,
                          const float* __restrict__ wx, const float* __restrict__ wy) {
    __shared__ __align__(16) float xs_s[16][64];
    __shared__ __align__(16) float ws_s[16][192];
    const float* src = blockIdx.y ? y : x;
    const float* w   = blockIdx.y ? wy : wx;
    float* dst       = blockIdx.y ? g_yin : g_xin;
    int tile = blockIdx.x;
    int b  = tile >> 6;
    int p0 = (tile & 63) * 64;
    int t  = threadIdx.x;
    int dg = t & 15;
    int pg = t >> 4;
    int d0 = dg * 12;
    int px = pg * 4;
    u64 acc2[4][6];
#pragma unroll
    for (int i = 0; i < 4; i++)
#pragma unroll
        for (int j = 0; j < 6; j++) acc2[i][j] = 0ull;

    for (int c0 = 0; c0 < DM; c0 += 16) {
        __syncthreads();
        for (int idx = t; idx < 16*64; idx += 256) {
            int cc = idx >> 6, j = idx & 63;
            xs_s[cc][j] = src[((size_t)(b*DM + c0 + cc))*LL + p0 + j];
        }
        for (int idx = t; idx < 16*192; idx += 256) {
            int cc = idx / 192, d = idx % 192;
            ws_s[cc][d] = w[(c0 + cc)*DI + d];
        }
        __syncthreads();
#pragma unroll
        for (int cc = 0; cc < 16; cc++) {
            float4 xv = *(const float4*)&xs_s[cc][px];
            ulonglong2 wq0 = *(const ulonglong2*)&ws_s[cc][d0];
            ulonglong2 wq1 = *(const ulonglong2*)&ws_s[cc][d0+4];
            ulonglong2 wq2 = *(const ulonglong2*)&ws_s[cc][d0+8];
            u64 wp[6] = {wq0.x, wq0.y, wq1.x, wq1.y, wq2.x, wq2.y};
            u64 xp[4] = {pk(xv.x,xv.x), pk(xv.y,xv.y), pk(xv.z,xv.z), pk(xv.w,xv.w)};
#pragma unroll
            for (int i = 0; i < 4; i++)
#pragma unroll
                for (int j = 0; j < 6; j++)
                    acc2[i][j] = fma2(xp[i], wp[j], acc2[i][j]);
        }
    }
#pragma unroll
    for (int i = 0; i < 4; i++) {
        float o[12];
#pragma unroll
        for (int j = 0; j < 6; j++) upk(acc2[i][j], o[2*j], o[2*j+1]);
        int p = p0 + px + i;
        float* op = dst + ((size_t)b*LL + p)*DI + d0;
        float4 q0 = make_float4(o[0], o[1], o[2], o[3]);
        float4 q1 = make_float4(o[4], o[5], o[6], o[7]);
        float4 q2 = make_float4(o[8], o[9], o[10], o[11]);
        *(float4*)(op + 0) = q0;
        *(float4*)(op + 4) = q1;
        *(float4*)(op + 8) = q2;
        if (blockIdx.y) {
            int tp = ((p & 63) << 6) | (p >> 6);
            float* ot = g_yinT + ((size_t)b*LL + tp)*DI + d0;
            *(float4*)(ot + 0) = q0;
            *(float4*)(ot + 4) = q1;
            *(float4*)(ot + 8) = q2;
        }
    }
}

// ---------------- kernel 2: x_proj as k1-style output-tile GEMM --------------
#define XS_PAD 68
#define WS_PAD 196
__global__ __launch_bounds__(256) void k2_xproj(const float* __restrict__ xpw) {
    __shared__ __align__(16) float xs_s[16][XS_PAD];
    __shared__ __align__(16) float ws_s[16][WS_PAD];
    int p0 = blockIdx.x * 64;
    int b  = blockIdx.y;
    int t  = threadIdx.x;
    int cg = t & 15;
    int pg = t >> 4;
    int c0 = cg * 12;
    int px = pg * 4;
    u64 acc2[4][6];
#pragma unroll
    for (int i = 0; i < 4; i++)
#pragma unroll
        for (int j = 0; j < 6; j++) acc2[i][j] = 0ull;

    for (int d0 = 0; d0 < DI; d0 += 16) {
        __syncthreads();
        for (int idx = t; idx < 16*64; idx += 256) {
            int dd = idx & 15, l = idx >> 4;
            xs_s[dd][l] = g_xin[((size_t)b*LL + p0 + l)*DI + d0 + dd];
        }
        for (int idx = t; idx < 16*192; idx += 256) {
            int dd = idx & 15, kcs = idx >> 4;
            int k = kcs / 48, cc = kcs % 48;
            ws_s[dd][kcs] = (cc < CPROJ) ? xpw[((size_t)(k*CPROJ + cc))*DI + d0 + dd] : 0.f;
        }
        __syncthreads();
#pragma unroll
        for (int dd = 0; dd < 16; dd++) {
            float4 xv = *(const float4*)&xs_s[dd][px];
            ulonglong2 wq0 = *(const ulonglong2*)&ws_s[dd][c0];
            ulonglong2 wq1 = *(const ulonglong2*)&ws_s[dd][c0+4];
            ulonglong2 wq2 = *(const ulonglong2*)&ws_s[dd][c0+8];
            u64 wp[6] = {wq0.x, wq0.y, wq1.x, wq1.y, wq2.x, wq2.y};
            u64 xp[4] = {pk(xv.x,xv.x), pk(xv.y,xv.y), pk(xv.z,xv.z), pk(xv.w,xv.w)};
#pragma unroll
            for (int i = 0; i < 4; i++)
#pragma unroll
                for (int j = 0; j < 6; j++)
                    acc2[i][j] = fma2(xp[i], wp[j], acc2[i][j]);
        }
    }

    int k  = cg >> 2;
    int cl = (cg & 3) * 12;
    size_t rowbase = (size_t)(b*KK + k)*LL;
#pragma unroll
    for (int i = 0; i < 4; i++) {
        int p = p0 + px + i;
        int l = inv_perm(k, p);
        float o[12];
#pragma unroll
        for (int j = 0; j < 6; j++) upk(acc2[i][j], o[2*j], o[2*j+1]);
        if (cl == 0) {
            float* dst = g_pj + (rowbase + l)*RR;
            *(float4*)(dst + 0) = make_float4(o[0], o[1], o[2], o[3]);
            *(float4*)(dst + 4) = make_float4(o[4], o[5], o[6], o[7]);
            *(float4*)(dst + 8) = make_float4(o[8], o[9], o[10], o[11]);
        } else if (cl == 12) {
            float* dst = g_Bs + (rowbase + l)*NS;
            *(float4*)(dst + 0) = make_float4(o[0], o[1], o[2], o[3]);
            *(float4*)(dst + 4) = make_float4(o[4], o[5], o[6], o[7]);
            *(float4*)(dst + 8) = make_float4(o[8], o[9], o[10], o[11]);
        } else if (cl == 24) {
            *(float4*)(g_Bs + (rowbase + l)*NS + 12) = make_float4(o[0], o[1], o[2], o[3]);
            *(float4*)(g_Cs + (rowbase + l)*NS + 0)  = make_float4(o[4], o[5], o[6], o[7]);
            *(float4*)(g_Cs + (rowbase + l)*NS + 4)  = make_float4(o[8], o[9], o[10], o[11]);
        } else {
            *(float4*)(g_Cs + (rowbase + l)*NS + 8)  = make_float4(o[0], o[1], o[2], o[3]);
            *(float4*)(g_Cs + (rowbase + l)*NS + 12) = make_float4(o[4], o[5], o[6], o[7]);
        }
    }
}

// u-stream: all 4 directions contiguous via yin / yinT
__device__ __forceinline__ const float* u_base(int k, int b, int l0, int d, int& ustep) {
    if (k == 0) { ustep =  DI; return g_yin  + ((size_t)b*LL + l0)*DI + d; }
    if (k == 1) { ustep =  DI; return g_yinT + ((size_t)b*LL + l0)*DI + d; }
    if (k == 2) { ustep = -DI; return g_yin  + ((size_t)b*LL + (LL-1-l0))*DI + d; }
    ustep = -DI; return g_yinT + ((size_t)b*LL + (LL-1-l0))*DI + d;
}

// y-output in PIXEL order: start pixel + uniform stride per direction
__device__ __forceinline__ float* y_base(int k, size_t bk, int l0, int d, int& ostep) {
    int pstart;
    if (k == 0)      { pstart = l0;                                  ostep =  DI;    }
    else if (k == 1) { pstart = ((l0 & 63) << 6) | (l0 >> 6);        ostep =  64*DI; }
    else if (k == 2) { pstart = LL - 1 - l0;                          ostep = -DI;    }
    else { int q = LL - 1 - l0; pstart = ((q & 63) << 6) | (q >> 6);  ostep = -64*DI; }
    return g_sy + (bk*LL + (size_t)pstart)*DI + d;
}

// delta recompute: two 3-deep fma2 chains (ILP) + softplus
__device__ __forceinline__ float delta_step(const u64* wp2, float bias, const float* pjrow){
    const u64* pj = (const u64*)pjrow;
    u64 a2 = fma2(wp2[0], pj[0], 0ull);
    u64 b2 = fma2(wp2[1], pj[1], 0ull);
    a2 = fma2(wp2[2], pj[2], a2);
    b2 = fma2(wp2[3], pj[3], b2);
    a2 = fma2(wp2[4], pj[4], a2);
    b2 = fma2(wp2[5], pj[5], b2);
    float alo, ahi, blo, bhi;
    upk(a2, alo, ahi); upk(b2, blo, bhi);
    return softplusf(bias + (alo + blo) + (ahi + bhi));
}

// ---- pass1: recursion + C-dot + y_local (pixel order) + chunk summaries -----
__global__ __launch_bounds__(192, 5) void k3_pass1() {
    __shared__ __align__(16) float sB[CT*NS];
    __shared__ __align__(16) float sC[CT*NS];
    __shared__ __align__(16) float sPJ[CT*RR];
    int c = blockIdx.x, k = blockIdx.y, b = blockIdx.z;
    int d = threadIdx.x;
    size_t bk = (size_t)(b*KK + k);
    int l0 = c * CT;
    {
        const float4* Bg = (const float4*)(g_Bs + (bk*LL + (size_t)l0)*NS);
        const float4* Cg = (const float4*)(g_Cs + (bk*LL + (size_t)l0)*NS);
        const float4* Pg = (const float4*)(g_pj + (bk*LL + (size_t)l0)*RR);
        float4* sB4 = (float4*)sB;
        float4* sC4 = (float4*)sC;
        float4* sP4 = (float4*)sPJ;
        for (int i = d; i < CT*NS/4; i += 192) { sB4[i] = Bg[i]; sC4[i] = Cg[i]; }
        for (int i = d; i < CT*RR/4; i += 192) sP4[i] = Pg[i];
    }
    __syncthreads();

    float* op; int ostep;
    op = y_base(k, bk, l0, d, ostep);
    int ustep;
    const float* up = u_base(k, b, l0, d, ustep);
    size_t ch = bk*DI + d;

    const float4* wr4 = (const float4*)(g_dtw + ((size_t)k*DI + d)*RR);
    float4 w0 = wr4[0], w1 = wr4[1], w2 = wr4[2];
    u64 wp2[6] = { pk(w0.x,w0.y), pk(w0.z,w0.w), pk(w1.x,w1.y),
                   pk(w1.z,w1.w), pk(w2.x,w2.y), pk(w2.z,w2.w) };
    float bias = g_dtb[k*DI + d];

    if (g_fast) {
        float an0 = g_anl2[((size_t)k*DI + d)*NS];
        u64 h2[8];
#pragma unroll
        for (int i = 0; i < 8; i++) h2[i] = 0ull;
        float S = 0.f;
#pragma unroll 4
        for (int t = 0; t < CT; t++) {
            float dlt = delta_step(wp2, bias, &sPJ[t*RR]);
            float uv  = up[(size_t)t*ustep];
            const u64* Bw = (const u64*)&sB[t*NS];
            const u64* Cw = (const u64*)&sC[t*NS];
            u64 P[8]; pows16p(ex2f(dlt * an0), P);
            float du = dlt * uv;
            u64 DU = pk(du, du);
            u64 Y0 = 0ull, Y1 = 0ull;
#pragma unroll
            for (int i = 0; i < 4; i++) {
                h2[2*i]   = fma2(P[2*i],   h2[2*i],   mul2(DU, Bw[2*i]));
                h2[2*i+1] = fma2(P[2*i+1], h2[2*i+1], mul2(DU, Bw[2*i+1]));
                Y0 = fma2(h2[2*i],   Cw[2*i],   Y0);
                Y1 = fma2(h2[2*i+1], Cw[2*i+1], Y1);
            }
            float y0l, y0h, y1l, y1h;
            upk(Y0, y0l, y0h); upk(Y1, y1l, y1h);
            op[(size_t)t*ostep] = (y0l + y1l) + (y0h + y1h);
            S += dlt;
        }
        u64* Hp = (u64*)(g_H + (ch*NC + c)*NS);
        u64* Pp = (u64*)(g_P + (ch*NC + c)*NS);
        u64 Q[8]; pows16p(ex2f(an0 * S), Q);
#pragma unroll
        for (int i = 0; i < 8; i++) { Hp[i] = h2[i]; Pp[i] = Q[i]; }
    } else {
        float an[NS];
        const float* ap = g_anl2 + ((size_t)k*DI + d)*NS;
#pragma unroll
        for (int n = 0; n < NS; n++) an[n] = ap[n];
        float h[NS];
#pragma unroll
        for (int n = 0; n < NS; n++) h[n] = 0.f;
        float S = 0.f;
        for (int t = 0; t < CT; t++) {
            float dlt = delta_step(wp2, bias, &sPJ[t*RR]);
            float uv  = up[(size_t)t*ustep];
            float du = dlt * uv;
            const float* Bp = &sB[t*NS];
            const float* Cp = &sC[t*NS];
            float y = 0.f;
#pragma unroll
            for (int n = 0; n < NS; n++) {
                h[n] = fmaf(ex2f(dlt*an[n]), h[n], du * Bp[n]);
                y = fmaf(h[n], Cp[n], y);
            }
            op[(size_t)t*ostep] = y;
            S += dlt;
        }
        float* Hp = g_H + (ch*NC + c)*NS;
        float* Pp = g_P + (ch*NC + c)*NS;
#pragma unroll
        for (int n = 0; n < NS; n++) { Hp[n] = h[n]; Pp[n] = ex2f(an[n]*S); }
    }
}

__global__ void k3_comb() {
    int t = blockIdx.x * blockDim.x + threadIdx.x;
    int n = t & 15;
    size_t ch = (size_t)(t >> 4);
    const float* __restrict__ Hp = g_H   + ch*NC*NS + n;
    const float* __restrict__ Pp = g_P   + ch*NC*NS + n;
    float*       __restrict__ Ip = g_Hin + ch*NC*NS + n;
    float h = 0.f;
#pragma unroll 4
    for (int c = 0; c < NC; c++) {
        Ip[c*NS] = h;
        h = fmaf(Pp[c*NS], h, Hp[c*NS]);
    }
}

// ---- pass2: chain-free carry correction (recomputes delta prefix) -----------
__global__ __launch_bounds__(192, 5) void k3_pass2() {
    __shared__ __align__(16) float sC[CT*NS];
    __shared__ __align__(16) float sPJ[CT*RR];
    int c = blockIdx.x, k = blockIdx.y, b = blockIdx.z;
    int d = threadIdx.x;
    size_t bk = (size_t)(b*KK + k);
    int l0 = c * CT;
    {
        const float4* Cg = (const float4*)(g_Cs + (bk*LL + (size_t)l0)*NS);
        const float4* Pg = (const float4*)(g_pj + (bk*LL + (size_t)l0)*RR);
        float4* sC4 = (float4*)sC;
        float4* sP4 = (float4*)sPJ;
        for (int i = d; i < CT*NS/4; i += 192) sC4[i] = Cg[i];
        for (int i = d; i < CT*RR/4; i += 192) sP4[i] = Pg[i];
    }
    __syncthreads();

    const float4* wr4 = (const float4*)(g_dtw + ((size_t)k*DI + d)*RR);
    float4 w0 = wr4[0], w1 = wr4[1], w2 = wr4[2];
    u64 wp2[6] = { pk(w0.x,w0.y), pk(w0.z,w0.w), pk(w1.x,w1.y),
                   pk(w1.z,w1.w), pk(w2.x,w2.y), pk(w2.z,w2.w) };
    float bias = g_dtb[k*DI + d];

    float* yp; int ostep;
    yp = y_base(k, bk, l0, d, ostep);
    size_t ch = bk*DI + d;

    if (g_fast) {
        float an0 = g_anl2[((size_t)k*DI + d)*NS];
        const u64* Ip = (const u64*)(g_Hin + (ch*NC + c)*NS);
        u64 hin[8];
#pragma unroll
        for (int i = 0; i < 8; i++) hin[i] = Ip[i];
        float S = 0.f;
#pragma unroll 4
        for (int t = 0; t < CT; t++) {
            S += delta_step(wp2, bias, &sPJ[t*RR]);
            u64 P[8]; pows16p(ex2f(an0 * S), P);
            const u64* Cw = (const u64*)&sC[t*NS];
            u64 Y0 = 0ull, Y1 = 0ull;
#pragma unroll
            for (int i = 0; i < 4; i++) {
                Y0 = fma2(mul2(P[2*i],   hin[2*i]),   Cw[2*i],   Y0);
                Y1 = fma2(mul2(P[2*i+1], hin[2*i+1]), Cw[2*i+1], Y1);
            }
            float y0l, y0h, y1l, y1h;
            upk(Y0, y0l, y0h); upk(Y1, y1l, y1h);
            yp[(size_t)t*ostep] += (y0l + y1l) + (y0h + y1h);
        }
    } else {
        float an[NS];
        const float* ap = g_anl2 + ((size_t)k*DI + d)*NS;
#pragma unroll
        for (int n = 0; n < NS; n++) an[n] = ap[n];
        const float* Ip = g_Hin + (ch*NC + c)*NS;
        float hin[NS];
#pragma unroll
        for (int n = 0; n < NS; n++) hin[n] = Ip[n];
        float S = 0.f;
        for (int t = 0; t < CT; t++) {
            S += delta_step(wp2, bias, &sPJ[t*RR]);
            const float* Cp = &sC[t*NS];
            float y = 0.f;
#pragma unroll
            for (int n = 0; n < NS; n++)
                y = fmaf(ex2f(an[n]*S) * hin[n], Cp[n], y);
            yp[(size_t)t*ostep] += y;
        }
    }
}

// ---------------- kernel 5: merge + LN + out_proj (float4 output stores) -----
__global__ __launch_bounds__(256) void k5_merge(
        const float* __restrict__ gamma, const float* __restrict__ beta,
        const float* __restrict__ opw, float* __restrict__ out) {
    __shared__ __align__(16) float ym_s[64*DI];
    __shared__ __align__(16) float W_s[16*DI];
    __shared__ float mu_s[64], rs_s[64];
    int b = blockIdx.y;
    int p0 = blockIdx.x * 64;
    int t = threadIdx.x;
    size_t bb = (size_t)b * KK;

    for (int idx = t; idx < 64*DI/4; idx += 256) {
        size_t off = (size_t)p0*DI + idx*4;
        float4 v0 = *(const float4*)&g_sy[((bb + 0)*LL)*DI + off];
        float4 v1 = *(const float4*)&g_sy[((bb + 1)*LL)*DI + off];
        float4 v2 = *(const float4*)&g_sy[((bb + 2)*LL)*DI + off];
        float4 v3 = *(const float4*)&g_sy[((bb + 3)*LL)*DI + off];
        float4 u  = *(const float4*)&g_yin[((size_t)b*LL)*DI + off];
        int dd = (idx*4) % DI;
        float4 ds = *(const float4*)&g_dsum[dd];
        float4 r;
        r.x = v0.x + v1.x + v2.x + v3.x + ds.x * u.x;
        r.y = v0.y + v1.y + v2.y + v3.y + ds.y * u.y;
        r.z = v0.z + v1.z + v2.z + v3.z + ds.z * u.z;
        r.w = v0.w + v1.w + v2.w + v3.w + ds.w * u.w;
        *(float4*)&ym_s[idx*4] = r;
    }
    __syncthreads();

    {
        int warp = t >> 5, lane = t & 31;
        int pl  = warp*8 + (lane >> 2);
        int sub = lane & 3;
        float s = 0.f, s2 = 0.f;
        for (int j = sub; j < DI; j += 4) { float v = ym_s[pl*DI + j]; s += v; s2 += v*v; }
        s  += __shfl_xor_sync(0xffffffffu, s, 2);  s2 += __shfl_xor_sync(0xffffffffu, s2, 2);
        s  += __shfl_xor_sync(0xffffffffu, s, 1);  s2 += __shfl_xor_sync(0xffffffffu, s2, 1);
        if (sub == 0) {
            float mu  = s * (1.f/DI);
            float var = s2 * (1.f/DI) - mu*mu;
            mu_s[pl] = mu;
            rs_s[pl] = rsqrtf(var + 1e-5f);
        }
    }
    __syncthreads();

    for (int idx = t; idx < 64*DI; idx += 256) {
        int pl = idx / DI, d = idx % DI;
        ym_s[idx] = (ym_s[idx] - mu_s[pl]) * rs_s[pl] * gamma[d] + beta[d];
    }

    int c0 = (t & 15) * 12;
    int px = (t >> 4) * 4;
    u64 acc2[4][6];
#pragma unroll
    for (int i = 0; i < 4; i++)
#pragma unroll
        for (int j = 0; j < 6; j++) acc2[i][j] = 0ull;

    for (int dc = 0; dc < DI; dc += 16) {
        __syncthreads();
        for (int idx = t; idx < 16*DI; idx += 256)
            W_s[idx] = opw[(dc + idx/DI)*DM + (idx % DI)];
        __syncthreads();
#pragma unroll
        for (int dd = 0; dd < 16; dd++) {
            ulonglong2 wq0 = *(const ulonglong2*)&W_s[dd*DI + c0];
            ulonglong2 wq1 = *(const ulonglong2*)&W_s[dd*DI + c0 + 4];
            ulonglong2 wq2 = *(const ulonglong2*)&W_s[dd*DI + c0 + 8];
            u64 wp[6] = {wq0.x, wq0.y, wq1.x, wq1.y, wq2.x, wq2.y};
#pragma unroll
            for (int i = 0; i < 4; i++) {
                float yv = ym_s[(px + i)*DI + dc + dd];
                u64 yp2 = pk(yv, yv);
#pragma unroll
                for (int j = 0; j < 6; j++)
                    acc2[i][j] = fma2(yp2, wp[j], acc2[i][j]);
            }
        }
    }
    {
        float o[4][12];
#pragma unroll
        for (int i = 0; i < 4; i++)
#pragma unroll
            for (int j = 0; j < 6; j++) upk(acc2[i][j], o[i][2*j], o[i][2*j+1]);
#pragma unroll
        for (int j = 0; j < 12; j++) {
            float4 v = make_float4(o[0][j], o[1][j], o[2][j], o[3][j]);
            *(float4*)&out[((size_t)(b*DM + c0 + j))*LL + p0 + px] = v;
        }
    }
}

extern "C" void kernel_launch(void* const* d_in, const int* in_sizes, int n_in,
                              void* d_out, int out_size) {
    const float* x    = (const float*)d_in[0];
    const float* y    = (const float*)d_in[1];
    const float* wx   = (const float*)d_in[2];
    const float* wy   = (const float*)d_in[3];
    const float* xpw  = (const float*)d_in[4];
    const float* dtw  = (const float*)d_in[5];
    const float* dtb  = (const float*)d_in[6];
    const float* Alog = (const float*)d_in[7];
    const float* Ds   = (const float*)d_in[8];
    const float* gam  = (const float*)d_in[9];
    const float* bet  = (const float*)d_in[10];
    const float* opw  = (const float*)d_in[11];
    float* out = (float*)d_out;

    k0_init<<<1, 256>>>(Alog, Ds, dtw, dtb);
    k1_inproj<<<dim3(256, 2), 256>>>(x, y, wx, wy);
    k2_xproj<<<dim3(LL/64, BATCH), 256>>>(xpw);
    k3_pass1<<<dim3(NC, KK, BATCH), 192>>>();
    k3_comb<<<192, 256>>>();
    k3_pass2<<<dim3(NC, KK, BATCH), 192>>>();
    k5_merge<<<dim3(LL/64, BATCH), 256>>>(gam, bet, opw, out);
}